// round 3
// baseline (speedup 1.0000x reference)
#include <cuda_runtime.h>
#include <math.h>

// Problem constants (fixed by the reference setup_inputs).
#define BB     64
#define SS     2048
#define HH     1024
#define H4     (HH / 4)        // 256 float4 per enc row
#define SPLITS 16
#define CHUNK  (SS / SPLITS)   // 128 seq rows per CTA
#define NT     256
#define NW     (NT / 32)       // 8 warps
#define RW     (CHUNK / NW)    // 16 rows per warp

// Scratch for split-K partials (static device globals: no allocation allowed).
__device__ float g_pm[BB * SPLITS];                 // per-split running max
__device__ float g_pl[BB * SPLITS];                 // per-split sum of exp
__device__ float g_pctx[(size_t)BB * SPLITS * HH];  // per-split partial context (4 MB)

// -----------------------------------------------------------------------------
// Pass 1: warp-per-row streaming with private online softmax (no barriers in
// the mainloop). grid = BB*SPLITS, block = NT. blockIdx.x = b*SPLITS + split.
// Each warp processes RW contiguous 4KB rows: lane l holds float4 columns
// {j*32 + l}. One shuffle-reduce per row. CTA-level combine happens once.
// -----------------------------------------------------------------------------
__global__ __launch_bounds__(NT, 2) void luong_pass1(
    const float* __restrict__ dec_h,
    const float* __restrict__ dec_c,
    const float* __restrict__ enc,
    float* __restrict__ scores_out)
{
    const int b     = blockIdx.x / SPLITS;
    const int split = blockIdx.x % SPLITS;
    const int t     = threadIdx.x;
    const int lane  = t & 31;
    const int w     = t >> 5;

    __shared__ float4 sm_dec[H4];          // combined dec state (4 KB)
    __shared__ float  sm_m[NW], sm_l[NW];
    __shared__ float  sm_scores[CHUNK];
    __shared__ float4 sm_acc[NW * H4];     // per-warp partial contexts (32 KB)

    // Build dec = h + c in smem (coalesced, once).
    {
        const float4* hp = (const float4*)(dec_h + (size_t)b * HH);
        const float4* cp = (const float4*)(dec_c + (size_t)b * HH);
        float4 a = hp[t], c = cp[t];
        sm_dec[t] = make_float4(a.x + c.x, a.y + c.y, a.z + c.z, a.w + c.w);
    }
    __syncthreads();

    const float4* erow = (const float4*)(enc + (size_t)b * SS * HH);
    const int s0 = split * CHUNK + w * RW;   // this warp's first row

    float  m = -INFINITY;
    float  l = 0.0f;
    float4 acc[8];
    #pragma unroll
    for (int j = 0; j < 8; ++j) acc[j] = make_float4(0.f, 0.f, 0.f, 0.f);

    // Preload row 0.
    float4 e[8];
    {
        const float4* rp = erow + (size_t)s0 * H4;
        #pragma unroll
        for (int j = 0; j < 8; ++j) e[j] = rp[j * 32 + lane];
    }

    for (int r = 0; r < RW; ++r) {
        // Prefetch next row while current row is consumed (keeps 8 LDG in flight).
        float4 en[8];
        if (r + 1 < RW) {
            const float4* rp = erow + (size_t)(s0 + r + 1) * H4;
            #pragma unroll
            for (int j = 0; j < 8; ++j) en[j] = rp[j * 32 + lane];
        }

        // Dot with smem-resident dec slice.
        float p = 0.f;
        #pragma unroll
        for (int j = 0; j < 8; ++j) {
            float4 d = sm_dec[j * 32 + lane];
            p += e[j].x * d.x + e[j].y * d.y + e[j].z * d.z + e[j].w * d.w;
        }
        // Warp reduce -> full row score in every lane.
        #pragma unroll
        for (int o = 16; o > 0; o >>= 1)
            p += __shfl_xor_sync(0xffffffffu, p, o);

        if (lane == 0) sm_scores[w * RW + r] = p;

        // Online softmax (warp-uniform branch; rescale is rare after warmup).
        if (p > m) {
            const float scale = __expf(m - p);   // first row: exp(-inf)=0
            l *= scale;
            #pragma unroll
            for (int j = 0; j < 8; ++j) {
                acc[j].x *= scale; acc[j].y *= scale;
                acc[j].z *= scale; acc[j].w *= scale;
            }
            m = p;
        }
        const float pe = __expf(p - m);
        l += pe;
        #pragma unroll
        for (int j = 0; j < 8; ++j) {
            acc[j].x += pe * e[j].x;
            acc[j].y += pe * e[j].y;
            acc[j].z += pe * e[j].z;
            acc[j].w += pe * e[j].w;
        }

        #pragma unroll
        for (int j = 0; j < 8; ++j) e[j] = en[j];
    }

    // ---- One-time CTA combine across the 8 warps ----
    if (lane == 0) { sm_m[w] = m; sm_l[w] = l; }
    __syncthreads();

    float gm = sm_m[0];
    #pragma unroll
    for (int i = 1; i < NW; ++i) gm = fmaxf(gm, sm_m[i]);
    float gl = 0.f;
    #pragma unroll
    for (int i = 0; i < NW; ++i) gl += sm_l[i] * __expf(sm_m[i] - gm);

    const float ws = __expf(m - gm);
    #pragma unroll
    for (int j = 0; j < 8; ++j) {
        float4 a = acc[j];
        a.x *= ws; a.y *= ws; a.z *= ws; a.w *= ws;
        sm_acc[w * H4 + j * 32 + lane] = a;
    }
    __syncthreads();

    // Thread t sums column t across the 8 warps and emits the split partial.
    float4 s = make_float4(0.f, 0.f, 0.f, 0.f);
    #pragma unroll
    for (int i = 0; i < NW; ++i) {
        float4 a = sm_acc[i * H4 + t];
        s.x += a.x; s.y += a.y; s.z += a.z; s.w += a.w;
    }
    ((float4*)g_pctx)[(size_t)blockIdx.x * H4 + t] = s;
    if (t == 0) { g_pm[blockIdx.x] = gm; g_pl[blockIdx.x] = gl; }

    // Coalesced raw-score stash (threads 0..127).
    if (t < CHUNK)
        scores_out[(size_t)b * SS + split * CHUNK + t] = sm_scores[t];
}

// -----------------------------------------------------------------------------
// Pass 2: combine split partials; write context and finalize weights in-place.
// grid = BB*2 (part = half of columns / half of sequence), block = NT.
// Two threads per float4 column, each summing 8 of the 16 splits, pair-merged
// via shfl. Weights: 4 coalesced elements per thread.
// -----------------------------------------------------------------------------
__global__ __launch_bounds__(NT) void luong_pass2(
    float* __restrict__ ctx_out,
    float* __restrict__ weights_io)
{
    const int b    = blockIdx.x >> 1;
    const int part = blockIdx.x & 1;
    const int t    = threadIdx.x;

    // Global max / normalizer across splits (redundant per thread; tiny).
    float m = -INFINITY;
    #pragma unroll
    for (int i = 0; i < SPLITS; ++i)
        m = fmaxf(m, g_pm[b * SPLITS + i]);

    float wgt[SPLITS];
    float l = 0.f;
    #pragma unroll
    for (int i = 0; i < SPLITS; ++i) {
        wgt[i] = __expf(g_pm[b * SPLITS + i] - m);
        l += g_pl[b * SPLITS + i] * wgt[i];
    }
    const float invl = 1.0f / l;

    // Context: column c handled by a thread pair (t even/odd -> splits 0-7 / 8-15).
    const int c  = part * 128 + (t >> 1);
    const int h0 = (t & 1) * 8;
    float4 a = make_float4(0.f, 0.f, 0.f, 0.f);
    #pragma unroll
    for (int i = 0; i < 8; ++i) {
        const float wv = wgt[h0 + i];
        float4 p = ((const float4*)g_pctx)[(size_t)(b * SPLITS + h0 + i) * H4 + c];
        a.x += wv * p.x; a.y += wv * p.y; a.z += wv * p.z; a.w += wv * p.w;
    }
    a.x += __shfl_xor_sync(0xffffffffu, a.x, 1);
    a.y += __shfl_xor_sync(0xffffffffu, a.y, 1);
    a.z += __shfl_xor_sync(0xffffffffu, a.z, 1);
    a.w += __shfl_xor_sync(0xffffffffu, a.w, 1);
    if ((t & 1) == 0) {
        a.x *= invl; a.y *= invl; a.z *= invl; a.w *= invl;
        ((float4*)ctx_out)[(size_t)b * H4 + c] = a;
    }

    // Weights finalize: raw score -> exp(s - m) / l. 1024 per part, coalesced.
    #pragma unroll
    for (int i = 0; i < 4; ++i) {
        const size_t idx = (size_t)b * SS + part * 1024 + i * NT + t;
        weights_io[idx] = __expf(weights_io[idx] - m) * invl;
    }
}

// -----------------------------------------------------------------------------
// Harness entry. Inputs (metadata order): dec_state_h [B,H] f32,
// dec_state_c [B,H] f32, enc_output [B,S,H] f32.
// Output: concat(context_vector [B,H], attention_weights [B,S,1]) f32.
// -----------------------------------------------------------------------------
extern "C" void kernel_launch(void* const* d_in, const int* in_sizes, int n_in,
                              void* d_out, int out_size)
{
    (void)in_sizes; (void)n_in; (void)out_size;
    const float* dec_h = (const float*)d_in[0];
    const float* dec_c = (const float*)d_in[1];
    const float* enc   = (const float*)d_in[2];
    float* out = (float*)d_out;
    float* ctx = out;                       // [B, H]
    float* wts = out + (size_t)BB * HH;     // [B, S, 1]

    luong_pass1<<<BB * SPLITS, NT>>>(dec_h, dec_c, enc, wts);
    luong_pass2<<<BB * 2, NT>>>(ctx, wts);
}